// round 5
// baseline (speedup 1.0000x reference)
#include <cuda_runtime.h>
#include <cuda_bf16.h>
#include <cstdint>
#include <math.h>

#define H      256
#define E      300
#define S_SENT 1024
#define L_W    64
#define NH3    768
#define NTOPIC 100
#define NTGT   5

typedef unsigned long long u64;

// ---------------- scratch ----------------
__device__ float g_dq[10 * NH3];
__device__ float g_pre[S_SENT * (L_W - 1) * NH3];
__device__ float g_leaf[S_SENT * NH3];
__device__ float g_h[S_SENT * H];
__device__ float g_pA[S_SENT * NH3];
__device__ float g_pB[S_SENT * NH3];
__device__ float g_gi[S_SENT * NH3];
__device__ float g_hT[H];

__device__ __forceinline__ float sigf(float x) { return 1.0f / (1.0f + expf(-x)); }

// ---- packed fp32x2 helpers ----
__device__ __forceinline__ u64 pk2(float lo, float hi) {
    u64 r; asm("mov.b64 %0, {%1, %2};" : "=l"(r) : "f"(lo), "f"(hi)); return r;
}
__device__ __forceinline__ u64 ffma2(u64 a, u64 b, u64 c) {
    u64 d; asm("fma.rn.f32x2 %0, %1, %2, %3;" : "=l"(d) : "l"(a), "l"(b), "l"(c)); return d;
}
__device__ __forceinline__ float pairsum(u64 v) {
    float x, y; asm("mov.b64 {%0, %1}, %2;" : "=f"(x), "=f"(y) : "l"(v)); return x + y;
}

// ---------------- dep-type table ----------------
__global__ void prep_kernel(const float* __restrict__ D, const float* __restrict__ q) {
    __shared__ float qs[H];
    int t = blockIdx.x;
    if (threadIdx.x < H) qs[threadIdx.x] = q[t * H + threadIdx.x];
    __syncthreads();
    int j = threadIdx.x;
    const float* Drow = D + (size_t)j * H;
    float acc = 0.f;
#pragma unroll 8
    for (int k = 0; k < H; k++) acc += Drow[k] * qs[k];
    g_dq[t * NH3 + j] = acc;
}

// ---------------- Wx GEMM (gather), FFMA2, 128x64 tile ----------------
__global__ __launch_bounds__(256) void wx_kernel(
    const int* __restrict__ sidx, const int* __restrict__ dep,
    const float* __restrict__ idx2vec, const float* __restrict__ W,
    const float* __restrict__ bias) {
    __shared__ __align__(16) float As[10][132];
    __shared__ __align__(16) float Bs[10][72];
    __shared__ int   ridx[128];
    __shared__ float bsh[64];

    int tid = threadIdx.x;
    int m0 = blockIdx.y * 128, n0 = blockIdx.x * 64;
    if (tid < 128) ridx[tid] = sidx[m0 + tid];
    if (tid < 64) bsh[tid] = bias[n0 + tid];
    __syncthreads();

    u64 acc[8][4];
#pragma unroll
    for (int i = 0; i < 8; i++)
#pragma unroll
        for (int j = 0; j < 4; j++) acc[i][j] = 0ull;

    int mA = tid >> 1, khA = (tid & 1) * 5;
    int nB = tid >> 1, khB = (tid & 1) * 5;
    int tr = tid >> 4, tc = tid & 15;

    for (int kt = 0; kt < 30; kt++) {
        int k0 = kt * 10;
        const float* arow = idx2vec + (size_t)ridx[mA] * E + k0 + khA;
        float av5[5], bv5[5];
#pragma unroll
        for (int u = 0; u < 5; u++) av5[u] = arow[u];
        if (tid < 128) {
            const float* brow = W + (size_t)(n0 + nB) * E + k0 + khB;
#pragma unroll
            for (int u = 0; u < 5; u++) bv5[u] = brow[u];
        }
        __syncthreads();
#pragma unroll
        for (int u = 0; u < 5; u++) As[khA + u][mA] = av5[u];
        if (tid < 128) {
#pragma unroll
            for (int u = 0; u < 5; u++) Bs[khB + u][nB] = bv5[u];
        }
        __syncthreads();
#pragma unroll
        for (int kp = 0; kp < 5; kp++) {
            int kl = 2 * kp, kh = 2 * kp + 1;
            float4 aL0 = *(const float4*)&As[kl][tr * 8];
            float4 aL1 = *(const float4*)&As[kl][tr * 8 + 4];
            float4 aH0 = *(const float4*)&As[kh][tr * 8];
            float4 aH1 = *(const float4*)&As[kh][tr * 8 + 4];
            float4 bL  = *(const float4*)&Bs[kl][tc * 4];
            float4 bH  = *(const float4*)&Bs[kh][tc * 4];
            u64 ap[8], bp[4];
            ap[0] = pk2(aL0.x, aH0.x); ap[1] = pk2(aL0.y, aH0.y);
            ap[2] = pk2(aL0.z, aH0.z); ap[3] = pk2(aL0.w, aH0.w);
            ap[4] = pk2(aL1.x, aH1.x); ap[5] = pk2(aL1.y, aH1.y);
            ap[6] = pk2(aL1.z, aH1.z); ap[7] = pk2(aL1.w, aH1.w);
            bp[0] = pk2(bL.x, bH.x); bp[1] = pk2(bL.y, bH.y);
            bp[2] = pk2(bL.z, bH.z); bp[3] = pk2(bL.w, bH.w);
#pragma unroll
            for (int i = 0; i < 8; i++)
#pragma unroll
                for (int j = 0; j < 4; j++) acc[i][j] = ffma2(ap[i], bp[j], acc[i][j]);
        }
    }

#pragma unroll
    for (int i = 0; i < 8; i++) {
        int m = m0 + tr * 8 + i;
        int s = m >> 6, l = m & 63;
        int dj = (l == 63) ? 9 : dep[s * 63 + l];
        const float* dqrow = g_dq + dj * NH3 + n0 + tc * 4;
        float* outr = ((l == 63) ? (g_leaf + (size_t)s * NH3)
                                 : (g_pre + (size_t)(s * 63 + l) * NH3)) + n0 + tc * 4;
        float4 dq4 = *(const float4*)dqrow;
        float4 v;
        v.x = pairsum(acc[i][0]) + bsh[tc * 4 + 0] + dq4.x;
        v.y = pairsum(acc[i][1]) + bsh[tc * 4 + 1] + dq4.y;
        v.z = pairsum(acc[i][2]) + bsh[tc * 4 + 2] + dq4.z;
        v.w = pairsum(acc[i][3]) + bsh[tc * 4 + 3] + dq4.w;
        *(float4*)outr = v;
    }
}

// ---------------- persistent tree kernel v2: cp.async-streamed U ----------------
// 128 CTAs x 8 sentences. U streamed per step as 8 tiles (32 k-cols x 768 rows),
// row stride 34 floats (8B-aligned rows; LDS.64 k-pair reads conflict-free per
// 16-lane phase). cp.async 8B, double-buffered, 2-deep commit pipeline.
#define SPT 8
#define TROW 34
#define TILE_WORDS (768 * TROW)
#define TREE_SMEM (2 * TILE_WORDS * 4 + SPT * H * 4)

__device__ __forceinline__ void tree_issue_tile(float* dst, const float* U,
                                                int kt, int c8, int jr) {
    int k0 = kt * 32;
    const float* src = U + (size_t)jr * H + k0 + c8 * 2;
    float* d = dst + jr * TROW + c8 * 2;
#pragma unroll
    for (int p = 0; p < 48; p++) {
        unsigned ds = (unsigned)__cvta_generic_to_shared(d + p * 16 * TROW);
        asm volatile("cp.async.ca.shared.global [%0], [%1], 8;"
                     :: "r"(ds), "l"(src + (size_t)p * 16 * H));
    }
    asm volatile("cp.async.commit_group;" ::: "memory");
}

__global__ __launch_bounds__(256) void tree_kernel(const float* __restrict__ U) {
    extern __shared__ __align__(16) float tsm[];
    float* Ut0 = tsm;
    float* Ut1 = tsm + TILE_WORDS;
    float* hsh = tsm + 2 * TILE_WORDS;        // [SPT][H]

    int tid = threadIdx.x;
    int s0 = blockIdx.x * SPT;

    // leaf init
    for (int e = tid; e < SPT * H; e += 256) {
        int s = e >> 8, i = e & 255;
        const float* r = g_leaf + (size_t)(s0 + s) * NH3;
        hsh[s * H + i] = tanhf(sigf(r[256 + i]) * tanhf(r[512 + i]));
    }

    int c8 = tid & 15;        // 8B chunk within 128B k-segment
    int jr = tid >> 4;        // base row 0..15

    tree_issue_tile(Ut0, U, 0, c8, jr);       // tile 0 -> buf 0

    int gt = 0;                                // global tile counter
    for (int k = 62; k >= 0; k--) {
        // prefetch pre rows for this step (consumed after the k-loop)
        float pre0[SPT], pre1[SPT], pre2[SPT];
#pragma unroll
        for (int s = 0; s < SPT; s++) {
            const float* pr = g_pre + ((size_t)(s0 + s) * 63 + k) * NH3;
            pre0[s] = pr[tid]; pre1[s] = pr[256 + tid]; pre2[s] = pr[512 + tid];
        }

        u64 acc0[SPT], acc1[SPT], acc2[SPT];
#pragma unroll
        for (int s = 0; s < SPT; s++) { acc0[s] = 0ull; acc1[s] = 0ull; acc2[s] = 0ull; }

        for (int kt = 0; kt < 8; kt++, gt++) {
            float* Ub = (gt & 1) ? Ut1 : Ut0;
            float* Un = (gt & 1) ? Ut0 : Ut1;
            // issue tile gt+1 into the other buffer (its previous compute
            // finished before the trailing __syncthreads of last iteration)
            tree_issue_tile(Un, U, (gt + 1) & 7, c8, jr);
            asm volatile("cp.async.wait_group 1;" ::: "memory");   // tile gt ready
            __syncthreads();                                       // visibility + hsh ordering
#pragma unroll
            for (int kp = 0; kp < 16; kp++) {
                u64 u0 = *(const u64*)&Ub[tid * TROW + 2 * kp];
                u64 u1 = *(const u64*)&Ub[(tid + 256) * TROW + 2 * kp];
                u64 u2 = *(const u64*)&Ub[(tid + 512) * TROW + 2 * kp];
                int kg = kt * 16 + kp;
#pragma unroll
                for (int s = 0; s < SPT; s++) {
                    u64 hp = *(const u64*)&hsh[s * H + 2 * kg];
                    acc0[s] = ffma2(u0, hp, acc0[s]);
                    acc1[s] = ffma2(u1, hp, acc1[s]);
                    acc2[s] = ffma2(u2, hp, acc2[s]);
                }
            }
            __syncthreads();   // compute on Ub done before it is refilled next iter
        }
        // elementwise update (all compute for this step complete)
#pragma unroll
        for (int s = 0; s < SPT; s++) {
            float t0 = pairsum(acc0[s]) + pre0[s];
            float t1 = pairsum(acc1[s]) + pre1[s];
            float t2 = pairsum(acc2[s]) + pre2[s];
            float hc = hsh[s * H + tid];
            hsh[s * H + tid] = tanhf(sigf(t1) * tanhf(t2) + sigf(t0) * hc);
        }
        // next tile iteration's __syncthreads orders these writes vs reads
    }
    __syncthreads();
    for (int e = tid; e < SPT * H; e += 256) {
        int s = e >> 8, i = e & 255;
        g_h[(size_t)(s0 + s) * H + i] = hsh[s * H + i];
    }
}

// ---------------- C_half = g_h @ B^T (once, for GRU gi) ----------------
__global__ __launch_bounds__(256) void ab_gemm(const float* __restrict__ B) {
    __shared__ float As[16][132];
    __shared__ float Bs[16][72];
    int tid = threadIdx.x;
    int n0 = blockIdx.x * 64, m0 = blockIdx.y * 128, kb = blockIdx.z * 128;

    float acc[8][4];
#pragma unroll
    for (int i = 0; i < 8; i++)
#pragma unroll
        for (int j = 0; j < 4; j++) acc[i][j] = 0.f;

    int mA = tid >> 1, khA = (tid & 1) * 8;
    int nB = tid >> 2, kqB = (tid & 3) * 4;
    int tr = tid >> 4, tc = tid & 15;

    for (int it = 0; it < 8; it++) {
        int k0 = kb + it * 16;
        float4 a0 = *(const float4*)(g_h + (size_t)(m0 + mA) * H + k0 + khA);
        float4 a1 = *(const float4*)(g_h + (size_t)(m0 + mA) * H + k0 + khA + 4);
        float4 b0 = *(const float4*)(B + (size_t)(n0 + nB) * H + k0 + kqB);
        __syncthreads();
        As[khA + 0][mA] = a0.x; As[khA + 1][mA] = a0.y;
        As[khA + 2][mA] = a0.z; As[khA + 3][mA] = a0.w;
        As[khA + 4][mA] = a1.x; As[khA + 5][mA] = a1.y;
        As[khA + 6][mA] = a1.z; As[khA + 7][mA] = a1.w;
        Bs[kqB + 0][nB] = b0.x; Bs[kqB + 1][nB] = b0.y;
        Bs[kqB + 2][nB] = b0.z; Bs[kqB + 3][nB] = b0.w;
        __syncthreads();
#pragma unroll
        for (int kk = 0; kk < 16; kk++) {
            float4 a0v = *(const float4*)&As[kk][tr * 8];
            float4 a1v = *(const float4*)&As[kk][tr * 8 + 4];
            float4 bv = *(const float4*)&Bs[kk][tc * 4];
            float av[8] = {a0v.x, a0v.y, a0v.z, a0v.w, a1v.x, a1v.y, a1v.z, a1v.w};
#pragma unroll
            for (int i = 0; i < 8; i++) {
                acc[i][0] += av[i] * bv.x;
                acc[i][1] += av[i] * bv.y;
                acc[i][2] += av[i] * bv.z;
                acc[i][3] += av[i] * bv.w;
            }
        }
    }
    float* Cw = blockIdx.z ? g_pB : g_pA;
#pragma unroll
    for (int i = 0; i < 8; i++) {
        float4 v = make_float4(acc[i][0], acc[i][1], acc[i][2], acc[i][3]);
        *(float4*)(Cw + (size_t)(m0 + tr * 8 + i) * NH3 + n0 + tc * 4) = v;
    }
}

// ---------------- gi = sv @ wih^T + bih ----------------
__global__ void gi_combine_kernel(const float* __restrict__ bih) {
    int idx = blockIdx.x * 256 + threadIdx.x;
    int n = idx % NH3;
    g_gi[idx] = g_pA[idx] + g_pB[idx] + bih[n];
}

// ---------------- GRU: 8-CTA cluster, register-resident whh, gh PUSH ----------------
__device__ __forceinline__ uint32_t smem_u32(const void* p) {
    return (uint32_t)__cvta_generic_to_shared(p);
}
__device__ __forceinline__ uint32_t mapa_u32(uint32_t a, uint32_t r) {
    uint32_t o;
    asm("mapa.shared::cluster.u32 %0, %1, %2;" : "=r"(o) : "r"(a), "r"(r));
    return o;
}
__device__ __forceinline__ void st_remote(uint32_t a, float v) {
    asm volatile("st.shared::cluster.f32 [%0], %1;" :: "r"(a), "f"(v) : "memory");
}
__device__ __forceinline__ void cluster_barrier() {
    asm volatile("barrier.cluster.arrive.aligned;" ::: "memory");
    asm volatile("barrier.cluster.wait.aligned;" ::: "memory");
}

__global__ void __cluster_dims__(8, 1, 1) __launch_bounds__(256, 1)
gru_kernel(const float* __restrict__ whh, const float* __restrict__ bhh,
           const float* __restrict__ h0) {
    __shared__ __align__(16) float hsh[H];
    __shared__ float ghsh[2][NH3];

    int tid = threadIdx.x;
    unsigned rank;
    asm("mov.u32 %0, %%cluster_ctarank;" : "=r"(rank));
    int g = tid >> 3, p = tid & 7;
    int jbase = (int)rank * 96 + g * 3;

    float w[3][32], bh[3];
#pragma unroll
    for (int c = 0; c < 3; c++) {
        int j = jbase + c;
        bh[c] = bhh[j];
        const float4* wr = (const float4*)(whh + (size_t)j * H + p * 32);
#pragma unroll
        for (int u = 0; u < 8; u++) {
            float4 v = wr[u];
            w[c][4 * u] = v.x; w[c][4 * u + 1] = v.y;
            w[c][4 * u + 2] = v.z; w[c][4 * u + 3] = v.w;
        }
    }
    hsh[tid] = h0[tid];

    uint32_t padr[2][8];
    if (p == 0) {
#pragma unroll
        for (int par = 0; par < 2; par++)
#pragma unroll
            for (int r8 = 0; r8 < 8; r8++)
                padr[par][r8] = mapa_u32(smem_u32(&ghsh[par][jbase]), (uint32_t)r8);
    }

    for (int t = 0; t < S_SENT; t++) {
        __syncthreads();
        int par = t & 1;
        const float* gir = g_gi + (size_t)t * NH3;
        float gi0 = __ldg(gir + tid), gi1 = __ldg(gir + 256 + tid), gi2 = __ldg(gir + 512 + tid);

        float hv[32];
        const float4* hp = (const float4*)(hsh + p * 32);
#pragma unroll
        for (int u = 0; u < 8; u++) {
            float4 v = hp[u];
            hv[4 * u] = v.x; hv[4 * u + 1] = v.y;
            hv[4 * u + 2] = v.z; hv[4 * u + 3] = v.w;
        }
        float a0 = 0.f, a1 = 0.f, a2 = 0.f;
#pragma unroll
        for (int u = 0; u < 32; u++) {
            a0 += w[0][u] * hv[u];
            a1 += w[1][u] * hv[u];
            a2 += w[2][u] * hv[u];
        }
#pragma unroll
        for (int off = 4; off > 0; off >>= 1) {
            a0 += __shfl_down_sync(0xffffffffu, a0, off, 8);
            a1 += __shfl_down_sync(0xffffffffu, a1, off, 8);
            a2 += __shfl_down_sync(0xffffffffu, a2, off, 8);
        }
        if (p == 0) {
            float v0 = a0 + bh[0], v1 = a1 + bh[1], v2 = a2 + bh[2];
#pragma unroll
            for (int r8 = 0; r8 < 8; r8++) {
                uint32_t a = padr[par][r8];
                st_remote(a, v0);
                st_remote(a + 4, v1);
                st_remote(a + 8, v2);
            }
        }
        cluster_barrier();

        float gh0 = ghsh[par][tid];
        float gh1 = ghsh[par][256 + tid];
        float gh2 = ghsh[par][512 + tid];
        float hh = hsh[tid];
        float r = sigf(gi0 + gh0);
        float z = sigf(gi1 + gh1);
        float n = tanhf(gi2 + r * gh2);
        hsh[tid] = (1.0f - z) * n + z * hh;
    }
    __syncthreads();
    if (rank == 0) g_hT[tid] = hsh[tid];
}

// ---------------- final: topic, gate, classifier, softmax ----------------
__global__ void final_kernel(const float* __restrict__ DT,
                             const float* __restrict__ gate_W, const float* __restrict__ gate_U,
                             const float* __restrict__ gate_b,
                             const float* __restrict__ mlp_W, const float* __restrict__ mlp_b,
                             const float* __restrict__ out_W, const float* __restrict__ out_b,
                             float* __restrict__ out) {
    __shared__ float tsh[H], hsh[H], vsh[H], lg[NTGT];
    int tid = threadIdx.x;
    float acc = mlp_b[tid];
    const float* mr = mlp_W + (size_t)tid * NTOPIC;
#pragma unroll 4
    for (int k = 0; k < NTOPIC; k++) acc += mr[k] * DT[k];
    tsh[tid] = tanhf(acc);
    hsh[tid] = g_hT[tid];
    __syncthreads();
    float ga = gate_b[tid], gb = gate_b[tid + H];
    const float* wr = gate_W + (size_t)tid * H;
    const float* wr2 = gate_W + (size_t)(tid + H) * H;
    const float* ur = gate_U + (size_t)tid * H;
    const float* ur2 = gate_U + (size_t)(tid + H) * H;
#pragma unroll 4
    for (int k = 0; k < H; k++) {
        float hk = hsh[k], tk = tsh[k];
        ga += wr[k] * hk + ur[k] * tk;
        gb += wr2[k] * hk + ur2[k] * tk;
    }
    vsh[tid] = tanhf(sigf(ga) * hsh[tid] + sigf(gb) * tsh[tid]);
    __syncthreads();
    int wix = tid >> 5, lane = tid & 31;
    if (wix < NTGT) {
        float a = 0.f;
        for (int k = lane; k < H; k += 32) a += out_W[wix * H + k] * vsh[k];
#pragma unroll
        for (int off = 16; off > 0; off >>= 1) a += __shfl_down_sync(0xffffffffu, a, off);
        if (lane == 0) lg[wix] = a + out_b[wix];
    }
    __syncthreads();
    if (tid == 0) {
        float mx = lg[0];
        for (int i = 1; i < NTGT; i++) mx = fmaxf(mx, lg[i]);
        float s = 0.f, e[NTGT];
        for (int i = 0; i < NTGT; i++) { e[i] = expf(lg[i] - mx); s += e[i]; }
        for (int i = 0; i < NTGT; i++) out[i] = e[i] / s;
    }
}

extern "C" void kernel_launch(void* const* d_in, const int* in_sizes, int n_in,
                              void* d_out, int out_size) {
    const int*   sidx    = (const int*)  d_in[0];
    const int*   dep     = (const int*)  d_in[1];
    const float* DT      = (const float*)d_in[2];
    const float* h0      = (const float*)d_in[3];
    const float* idx2vec = (const float*)d_in[4];
    const float* q       = (const float*)d_in[5];
    const float* W       = (const float*)d_in[6];
    const float* U       = (const float*)d_in[7];
    const float* D       = (const float*)d_in[8];
    const float* b       = (const float*)d_in[9];
    const float* gru_wih = (const float*)d_in[10];
    const float* gru_whh = (const float*)d_in[11];
    const float* gru_bih = (const float*)d_in[12];
    const float* gru_bhh = (const float*)d_in[13];
    const float* gate_W  = (const float*)d_in[14];
    const float* gate_U  = (const float*)d_in[15];
    const float* gate_b  = (const float*)d_in[16];
    const float* mlp_W   = (const float*)d_in[17];
    const float* mlp_b   = (const float*)d_in[18];
    const float* out_W   = (const float*)d_in[19];
    const float* out_b   = (const float*)d_in[20];
    float* out = (float*)d_out;

    cudaFuncSetAttribute(tree_kernel, cudaFuncAttributeMaxDynamicSharedMemorySize, TREE_SMEM);

    prep_kernel<<<10, NH3>>>(D, q);
    wx_kernel<<<dim3(12, 512), 256>>>(sidx, dep, idx2vec, W, b);

    tree_kernel<<<128, 256, TREE_SMEM>>>(U);

    ab_gemm<<<dim3(12, 8, 2), 256>>>(gru_wih);
    gi_combine_kernel<<<3072, 256>>>(gru_bih);

    gru_kernel<<<8, 256>>>(gru_whh, gru_bhh, h0);

    final_kernel<<<1, 256>>>(DT, gate_W, gate_U, gate_b, mlp_W, mlp_b, out_W, out_b, out);
}

// round 6
// speedup vs baseline: 1.0811x; 1.0811x over previous
#include <cuda_runtime.h>
#include <cuda_bf16.h>
#include <cstdint>
#include <math.h>

#define H      256
#define E      300
#define S_SENT 1024
#define L_W    64
#define NH3    768
#define NTOPIC 100
#define NTGT   5

typedef unsigned long long u64;

// ---------------- scratch ----------------
__device__ float g_dq[10 * NH3];
__device__ float g_pre[S_SENT * (L_W - 1) * NH3];
__device__ float g_leaf[S_SENT * NH3];
__device__ float g_h[S_SENT * H];
__device__ float g_pA[S_SENT * NH3];
__device__ float g_pB[S_SENT * NH3];
__device__ float g_pC[S_SENT * NH3];
__device__ float g_pD[S_SENT * NH3];
__device__ float g_gi[S_SENT * NH3];
__device__ float g_hT[H];

__device__ __forceinline__ float sigf(float x) { return 1.0f / (1.0f + expf(-x)); }

// ---- packed fp32x2 helpers ----
__device__ __forceinline__ u64 pk2(float lo, float hi) {
    u64 r; asm("mov.b64 %0, {%1, %2};" : "=l"(r) : "f"(lo), "f"(hi)); return r;
}
__device__ __forceinline__ u64 ffma2(u64 a, u64 b, u64 c) {
    u64 d; asm("fma.rn.f32x2 %0, %1, %2, %3;" : "=l"(d) : "l"(a), "l"(b), "l"(c)); return d;
}
__device__ __forceinline__ float pairsum(u64 v) {
    float x, y; asm("mov.b64 {%0, %1}, %2;" : "=f"(x), "=f"(y) : "l"(v)); return x + y;
}

// ---------------- dep-type table ----------------
__global__ void prep_kernel(const float* __restrict__ D, const float* __restrict__ q) {
    __shared__ float qs[H];
    int t = blockIdx.x;
    if (threadIdx.x < H) qs[threadIdx.x] = q[t * H + threadIdx.x];
    __syncthreads();
    int j = threadIdx.x;
    const float* Drow = D + (size_t)j * H;
    float acc = 0.f;
#pragma unroll 8
    for (int k = 0; k < H; k++) acc += Drow[k] * qs[k];
    g_dq[t * NH3 + j] = acc;
}

// ---------------- Wx GEMM (gather), FFMA2, 128x64 tile ----------------
__global__ __launch_bounds__(256) void wx_kernel(
    const int* __restrict__ sidx, const int* __restrict__ dep,
    const float* __restrict__ idx2vec, const float* __restrict__ W,
    const float* __restrict__ bias) {
    __shared__ __align__(16) float As[10][132];
    __shared__ __align__(16) float Bs[10][72];
    __shared__ int   ridx[128];
    __shared__ float bsh[64];

    int tid = threadIdx.x;
    int m0 = blockIdx.y * 128, n0 = blockIdx.x * 64;
    if (tid < 128) ridx[tid] = sidx[m0 + tid];
    if (tid < 64) bsh[tid] = bias[n0 + tid];
    __syncthreads();

    u64 acc[8][4];
#pragma unroll
    for (int i = 0; i < 8; i++)
#pragma unroll
        for (int j = 0; j < 4; j++) acc[i][j] = 0ull;

    int mA = tid >> 1, khA = (tid & 1) * 5;
    int nB = tid >> 1, khB = (tid & 1) * 5;
    int tr = tid >> 4, tc = tid & 15;

    for (int kt = 0; kt < 30; kt++) {
        int k0 = kt * 10;
        const float* arow = idx2vec + (size_t)ridx[mA] * E + k0 + khA;
        float av5[5], bv5[5];
#pragma unroll
        for (int u = 0; u < 5; u++) av5[u] = arow[u];
        if (tid < 128) {
            const float* brow = W + (size_t)(n0 + nB) * E + k0 + khB;
#pragma unroll
            for (int u = 0; u < 5; u++) bv5[u] = brow[u];
        }
        __syncthreads();
#pragma unroll
        for (int u = 0; u < 5; u++) As[khA + u][mA] = av5[u];
        if (tid < 128) {
#pragma unroll
            for (int u = 0; u < 5; u++) Bs[khB + u][nB] = bv5[u];
        }
        __syncthreads();
#pragma unroll
        for (int kp = 0; kp < 5; kp++) {
            int kl = 2 * kp, kh = 2 * kp + 1;
            float4 aL0 = *(const float4*)&As[kl][tr * 8];
            float4 aL1 = *(const float4*)&As[kl][tr * 8 + 4];
            float4 aH0 = *(const float4*)&As[kh][tr * 8];
            float4 aH1 = *(const float4*)&As[kh][tr * 8 + 4];
            float4 bL  = *(const float4*)&Bs[kl][tc * 4];
            float4 bH  = *(const float4*)&Bs[kh][tc * 4];
            u64 ap[8], bp[4];
            ap[0] = pk2(aL0.x, aH0.x); ap[1] = pk2(aL0.y, aH0.y);
            ap[2] = pk2(aL0.z, aH0.z); ap[3] = pk2(aL0.w, aH0.w);
            ap[4] = pk2(aL1.x, aH1.x); ap[5] = pk2(aL1.y, aH1.y);
            ap[6] = pk2(aL1.z, aH1.z); ap[7] = pk2(aL1.w, aH1.w);
            bp[0] = pk2(bL.x, bH.x); bp[1] = pk2(bL.y, bH.y);
            bp[2] = pk2(bL.z, bH.z); bp[3] = pk2(bL.w, bH.w);
#pragma unroll
            for (int i = 0; i < 8; i++)
#pragma unroll
                for (int j = 0; j < 4; j++) acc[i][j] = ffma2(ap[i], bp[j], acc[i][j]);
        }
    }

#pragma unroll
    for (int i = 0; i < 8; i++) {
        int m = m0 + tr * 8 + i;
        int s = m >> 6, l = m & 63;
        int dj = (l == 63) ? 9 : dep[s * 63 + l];
        const float* dqrow = g_dq + dj * NH3 + n0 + tc * 4;
        float* outr = ((l == 63) ? (g_leaf + (size_t)s * NH3)
                                 : (g_pre + (size_t)(s * 63 + l) * NH3)) + n0 + tc * 4;
        float4 dq4 = *(const float4*)dqrow;
        float4 v;
        v.x = pairsum(acc[i][0]) + bsh[tc * 4 + 0] + dq4.x;
        v.y = pairsum(acc[i][1]) + bsh[tc * 4 + 1] + dq4.y;
        v.z = pairsum(acc[i][2]) + bsh[tc * 4 + 2] + dq4.z;
        v.w = pairsum(acc[i][3]) + bsh[tc * 4 + 3] + dq4.w;
        *(float4*)outr = v;
    }
}

// ---------------- leaf: h = tanh(sigmoid(iu_i) * tanh(iu_u)) ----------------
__global__ void leaf_kernel() {
    int idx = blockIdx.x * 256 + threadIdx.x;
    int s = idx >> 8, i = idx & 255;
    const float* r = g_leaf + (size_t)s * NH3;
    g_h[idx] = tanhf(sigf(r[256 + i]) * tanhf(r[512 + i]));
}

// ---------------- C_part = g_h @ B^T  (M=1024, N=768, K=256, split-K 4) ----------------
// BM=128, BN=64, BK=16, 256 threads, 8x4 microtile. grid (12, 8, 4)
__global__ __launch_bounds__(256) void ab_gemm(const float* __restrict__ B) {
    __shared__ float As[16][132];
    __shared__ float Bs[16][72];
    int tid = threadIdx.x;
    int n0 = blockIdx.x * 64, m0 = blockIdx.y * 128, kb = blockIdx.z * 64;

    float acc[8][4];
#pragma unroll
    for (int i = 0; i < 8; i++)
#pragma unroll
        for (int j = 0; j < 4; j++) acc[i][j] = 0.f;

    int mA = tid >> 1, khA = (tid & 1) * 8;
    int nB = tid >> 2, kqB = (tid & 3) * 4;
    int tr = tid >> 4, tc = tid & 15;

    for (int it = 0; it < 4; it++) {
        int k0 = kb + it * 16;
        float4 a0 = *(const float4*)(g_h + (size_t)(m0 + mA) * H + k0 + khA);
        float4 a1 = *(const float4*)(g_h + (size_t)(m0 + mA) * H + k0 + khA + 4);
        float4 b0 = *(const float4*)(B + (size_t)(n0 + nB) * H + k0 + kqB);
        __syncthreads();
        As[khA + 0][mA] = a0.x; As[khA + 1][mA] = a0.y;
        As[khA + 2][mA] = a0.z; As[khA + 3][mA] = a0.w;
        As[khA + 4][mA] = a1.x; As[khA + 5][mA] = a1.y;
        As[khA + 6][mA] = a1.z; As[khA + 7][mA] = a1.w;
        Bs[kqB + 0][nB] = b0.x; Bs[kqB + 1][nB] = b0.y;
        Bs[kqB + 2][nB] = b0.z; Bs[kqB + 3][nB] = b0.w;
        __syncthreads();
#pragma unroll
        for (int kk = 0; kk < 16; kk++) {
            float4 a0v = *(const float4*)&As[kk][tr * 8];
            float4 a1v = *(const float4*)&As[kk][tr * 8 + 4];
            float4 bv = *(const float4*)&Bs[kk][tc * 4];
            float av[8] = {a0v.x, a0v.y, a0v.z, a0v.w, a1v.x, a1v.y, a1v.z, a1v.w};
#pragma unroll
            for (int i = 0; i < 8; i++) {
                acc[i][0] += av[i] * bv.x;
                acc[i][1] += av[i] * bv.y;
                acc[i][2] += av[i] * bv.z;
                acc[i][3] += av[i] * bv.w;
            }
        }
    }
    float* Cw = (blockIdx.z == 0) ? g_pA : (blockIdx.z == 1) ? g_pB
              : (blockIdx.z == 2) ? g_pC : g_pD;
#pragma unroll
    for (int i = 0; i < 8; i++) {
        float4 v = make_float4(acc[i][0], acc[i][1], acc[i][2], acc[i][3]);
        *(float4*)(Cw + (size_t)(m0 + tr * 8 + i) * NH3 + n0 + tc * 4) = v;
    }
}

// ---------------- tree elementwise step ----------------
__global__ void tree_elem_kernel(int k) {
    int idx = blockIdx.x * 256 + threadIdx.x;
    int s = idx >> 8, i = idx & 255;
    size_t pb = (size_t)(s * 63 + k) * NH3;
    size_t ab = (size_t)s * NH3;
    float t0 = g_pre[pb + i]       + g_pA[ab + i]       + g_pB[ab + i]       + g_pC[ab + i]       + g_pD[ab + i];
    float t1 = g_pre[pb + 256 + i] + g_pA[ab + 256 + i] + g_pB[ab + 256 + i] + g_pC[ab + 256 + i] + g_pD[ab + 256 + i];
    float t2 = g_pre[pb + 512 + i] + g_pA[ab + 512 + i] + g_pB[ab + 512 + i] + g_pC[ab + 512 + i] + g_pD[ab + 512 + i];
    float hc = g_h[idx];
    float f = sigf(t0) * hc;
    g_h[idx] = tanhf(sigf(t1) * tanhf(t2) + f);
}

// ---------------- gi = sv @ wih^T + bih ----------------
__global__ void gi_combine_kernel(const float* __restrict__ bih) {
    int idx = blockIdx.x * 256 + threadIdx.x;
    int n = idx % NH3;
    g_gi[idx] = g_pA[idx] + g_pB[idx] + g_pC[idx] + g_pD[idx] + bih[n];
}

// ---------------- GRU: 8-CTA cluster, register-resident whh ----------------
__device__ __forceinline__ uint32_t smem_u32(const void* p) {
    return (uint32_t)__cvta_generic_to_shared(p);
}
__device__ __forceinline__ uint32_t mapa_u32(uint32_t a, uint32_t r) {
    uint32_t o;
    asm("mapa.shared::cluster.u32 %0, %1, %2;" : "=r"(o) : "r"(a), "r"(r));
    return o;
}
__device__ __forceinline__ void st_remote(uint32_t a, float v) {
    asm volatile("st.shared::cluster.f32 [%0], %1;" :: "r"(a), "f"(v) : "memory");
}
__device__ __forceinline__ void cluster_barrier() {
    asm volatile("barrier.cluster.arrive.aligned;" ::: "memory");
    asm volatile("barrier.cluster.wait.aligned;" ::: "memory");
}

__global__ void __cluster_dims__(8, 1, 1) __launch_bounds__(256, 1)
gru_kernel(const float* __restrict__ whh, const float* __restrict__ bhh,
           const float* __restrict__ h0) {
    __shared__ __align__(16) float hsh[H];
    __shared__ float ghsh[2][NH3];

    int tid = threadIdx.x;
    unsigned rank;
    asm("mov.u32 %0, %%cluster_ctarank;" : "=r"(rank));
    int g = tid >> 3, p = tid & 7;
    int jbase = (int)rank * 96 + g * 3;

    // whh slice as packed pairs: 3 outputs x 16 k-pairs (k = p*32 + ...)
    u64 wp[3][16];
    float bh[3];
#pragma unroll
    for (int c = 0; c < 3; c++) {
        int j = jbase + c;
        bh[c] = bhh[j];
        const float4* wr = (const float4*)(whh + (size_t)j * H + p * 32);
#pragma unroll
        for (int u = 0; u < 8; u++) {
            float4 v = wr[u];
            wp[c][2 * u]     = pk2(v.x, v.y);
            wp[c][2 * u + 1] = pk2(v.z, v.w);
        }
    }
    hsh[tid] = h0[tid];

    // per-lane push target: this group's 3 values -> rank p's replica at jbase
    uint32_t padr[2];
#pragma unroll
    for (int par = 0; par < 2; par++)
        padr[par] = mapa_u32(smem_u32(&ghsh[par][jbase]), (uint32_t)p);

    for (int t = 0; t < S_SENT; t++) {
        __syncthreads();
        int par = t & 1;
        const float* gir = g_gi + (size_t)t * NH3;
        float gi0 = __ldg(gir + tid), gi1 = __ldg(gir + 256 + tid), gi2 = __ldg(gir + 512 + tid);

        u64 hvp[16];
        const float4* hp = (const float4*)(hsh + p * 32);
#pragma unroll
        for (int u = 0; u < 8; u++) {
            float4 v = hp[u];
            hvp[2 * u]     = pk2(v.x, v.y);
            hvp[2 * u + 1] = pk2(v.z, v.w);
        }
        u64 pa0 = 0ull, pa1 = 0ull, pa2 = 0ull;
#pragma unroll
        for (int u = 0; u < 16; u++) {
            pa0 = ffma2(wp[0][u], hvp[u], pa0);
            pa1 = ffma2(wp[1][u], hvp[u], pa1);
            pa2 = ffma2(wp[2][u], hvp[u], pa2);
        }
        float a0 = pairsum(pa0), a1 = pairsum(pa1), a2 = pairsum(pa2);
#pragma unroll
        for (int off = 4; off > 0; off >>= 1) {
            a0 += __shfl_xor_sync(0xffffffffu, a0, off, 8);
            a1 += __shfl_xor_sync(0xffffffffu, a1, off, 8);
            a2 += __shfl_xor_sync(0xffffffffu, a2, off, 8);
        }
        // every lane pushes the group's totals to its own target rank p
        {
            uint32_t a = padr[par];
            st_remote(a,     a0 + bh[0]);
            st_remote(a + 4, a1 + bh[1]);
            st_remote(a + 8, a2 + bh[2]);
        }
        cluster_barrier();

        float gh0 = ghsh[par][tid];
        float gh1 = ghsh[par][256 + tid];
        float gh2 = ghsh[par][512 + tid];
        float hh = hsh[tid];
        float r = sigf(gi0 + gh0);
        float z = sigf(gi1 + gh1);
        float n = tanhf(gi2 + r * gh2);
        hsh[tid] = (1.0f - z) * n + z * hh;
    }
    __syncthreads();
    if (rank == 0) g_hT[tid] = hsh[tid];
}

// ---------------- final: topic, gate, classifier, softmax ----------------
__global__ void final_kernel(const float* __restrict__ DT,
                             const float* __restrict__ gate_W, const float* __restrict__ gate_U,
                             const float* __restrict__ gate_b,
                             const float* __restrict__ mlp_W, const float* __restrict__ mlp_b,
                             const float* __restrict__ out_W, const float* __restrict__ out_b,
                             float* __restrict__ out) {
    __shared__ float tsh[H], hsh[H], vsh[H], lg[NTGT];
    int tid = threadIdx.x;
    float acc = mlp_b[tid];
    const float* mr = mlp_W + (size_t)tid * NTOPIC;
#pragma unroll 4
    for (int k = 0; k < NTOPIC; k++) acc += mr[k] * DT[k];
    tsh[tid] = tanhf(acc);
    hsh[tid] = g_hT[tid];
    __syncthreads();
    float ga = gate_b[tid], gb = gate_b[tid + H];
    const float* wr = gate_W + (size_t)tid * H;
    const float* wr2 = gate_W + (size_t)(tid + H) * H;
    const float* ur = gate_U + (size_t)tid * H;
    const float* ur2 = gate_U + (size_t)(tid + H) * H;
#pragma unroll 4
    for (int k = 0; k < H; k++) {
        float hk = hsh[k], tk = tsh[k];
        ga += wr[k] * hk + ur[k] * tk;
        gb += wr2[k] * hk + ur2[k] * tk;
    }
    vsh[tid] = tanhf(sigf(ga) * hsh[tid] + sigf(gb) * tsh[tid]);
    __syncthreads();
    int wix = tid >> 5, lane = tid & 31;
    if (wix < NTGT) {
        float a = 0.f;
        for (int k = lane; k < H; k += 32) a += out_W[wix * H + k] * vsh[k];
#pragma unroll
        for (int off = 16; off > 0; off >>= 1) a += __shfl_down_sync(0xffffffffu, a, off);
        if (lane == 0) lg[wix] = a + out_b[wix];
    }
    __syncthreads();
    if (tid == 0) {
        float mx = lg[0];
        for (int i = 1; i < NTGT; i++) mx = fmaxf(mx, lg[i]);
        float s = 0.f, e[NTGT];
        for (int i = 0; i < NTGT; i++) { e[i] = expf(lg[i] - mx); s += e[i]; }
        for (int i = 0; i < NTGT; i++) out[i] = e[i] / s;
    }
}

extern "C" void kernel_launch(void* const* d_in, const int* in_sizes, int n_in,
                              void* d_out, int out_size) {
    const int*   sidx    = (const int*)  d_in[0];
    const int*   dep     = (const int*)  d_in[1];
    const float* DT      = (const float*)d_in[2];
    const float* h0      = (const float*)d_in[3];
    const float* idx2vec = (const float*)d_in[4];
    const float* q       = (const float*)d_in[5];
    const float* W       = (const float*)d_in[6];
    const float* U       = (const float*)d_in[7];
    const float* D       = (const float*)d_in[8];
    const float* b       = (const float*)d_in[9];
    const float* gru_wih = (const float*)d_in[10];
    const float* gru_whh = (const float*)d_in[11];
    const float* gru_bih = (const float*)d_in[12];
    const float* gru_bhh = (const float*)d_in[13];
    const float* gate_W  = (const float*)d_in[14];
    const float* gate_U  = (const float*)d_in[15];
    const float* gate_b  = (const float*)d_in[16];
    const float* mlp_W   = (const float*)d_in[17];
    const float* mlp_b   = (const float*)d_in[18];
    const float* out_W   = (const float*)d_in[19];
    const float* out_b   = (const float*)d_in[20];
    float* out = (float*)d_out;

    prep_kernel<<<10, NH3>>>(D, q);
    wx_kernel<<<dim3(12, 512), 256>>>(sidx, dep, idx2vec, W, b);
    leaf_kernel<<<1024, 256>>>();

    for (int k = L_W - 2; k >= 0; k--) {
        ab_gemm<<<dim3(12, 8, 4), 256>>>(U);
        tree_elem_kernel<<<1024, 256>>>(k);
    }

    ab_gemm<<<dim3(12, 8, 4), 256>>>(gru_wih);
    gi_combine_kernel<<<3072, 256>>>(gru_bih);

    gru_kernel<<<8, 256>>>(gru_whh, gru_bhh, h0);

    final_kernel<<<1, 256>>>(DT, gate_W, gate_U, gate_b, mlp_W, mlp_b, out_W, out_b, out);
}

// round 7
// speedup vs baseline: 1.0870x; 1.0055x over previous
#include <cuda_runtime.h>
#include <cuda_bf16.h>
#include <cstdint>
#include <math.h>

#define H      256
#define E      300
#define S_SENT 1024
#define L_W    64
#define NH3    768
#define NTOPIC 100
#define NTGT   5

typedef unsigned long long u64;

// ---------------- scratch ----------------
__device__ float g_dq[10 * NH3];
__device__ float g_pre[S_SENT * (L_W - 1) * NH3];
__device__ float g_leaf[S_SENT * NH3];
__device__ float g_h[S_SENT * H];
__device__ float g_pA[S_SENT * NH3];
__device__ float g_pB[S_SENT * NH3];
__device__ float g_pC[S_SENT * NH3];
__device__ float g_pD[S_SENT * NH3];
__device__ float g_gi[S_SENT * NH3];
__device__ float g_hT[H];

__device__ __forceinline__ float sigf(float x) { return 1.0f / (1.0f + expf(-x)); }

// ---- packed fp32x2 helpers ----
__device__ __forceinline__ u64 pk2(float lo, float hi) {
    u64 r; asm("mov.b64 %0, {%1, %2};" : "=l"(r) : "f"(lo), "f"(hi)); return r;
}
__device__ __forceinline__ u64 ffma2(u64 a, u64 b, u64 c) {
    u64 d; asm("fma.rn.f32x2 %0, %1, %2, %3;" : "=l"(d) : "l"(a), "l"(b), "l"(c)); return d;
}
__device__ __forceinline__ float pairsum(u64 v) {
    float x, y; asm("mov.b64 {%0, %1}, %2;" : "=f"(x), "=f"(y) : "l"(v)); return x + y;
}

// ---------------- dep-type table ----------------
__global__ void prep_kernel(const float* __restrict__ D, const float* __restrict__ q) {
    __shared__ float qs[H];
    int t = blockIdx.x;
    if (threadIdx.x < H) qs[threadIdx.x] = q[t * H + threadIdx.x];
    __syncthreads();
    int j = threadIdx.x;
    const float* Drow = D + (size_t)j * H;
    float acc = 0.f;
#pragma unroll 8
    for (int k = 0; k < H; k++) acc += Drow[k] * qs[k];
    g_dq[t * NH3 + j] = acc;
}

// ---------------- Wx GEMM (gather), FFMA2, 128x64 tile ----------------
__global__ __launch_bounds__(256) void wx_kernel(
    const int* __restrict__ sidx, const int* __restrict__ dep,
    const float* __restrict__ idx2vec, const float* __restrict__ W,
    const float* __restrict__ bias) {
    __shared__ __align__(16) float As[10][132];
    __shared__ __align__(16) float Bs[10][72];
    __shared__ int   ridx[128];
    __shared__ float bsh[64];

    int tid = threadIdx.x;
    int m0 = blockIdx.y * 128, n0 = blockIdx.x * 64;
    if (tid < 128) ridx[tid] = sidx[m0 + tid];
    if (tid < 64) bsh[tid] = bias[n0 + tid];
    __syncthreads();

    u64 acc[8][4];
#pragma unroll
    for (int i = 0; i < 8; i++)
#pragma unroll
        for (int j = 0; j < 4; j++) acc[i][j] = 0ull;

    int mA = tid >> 1, khA = (tid & 1) * 5;
    int nB = tid >> 1, khB = (tid & 1) * 5;
    int tr = tid >> 4, tc = tid & 15;

    for (int kt = 0; kt < 30; kt++) {
        int k0 = kt * 10;
        const float* arow = idx2vec + (size_t)ridx[mA] * E + k0 + khA;
        float av5[5], bv5[5];
#pragma unroll
        for (int u = 0; u < 5; u++) av5[u] = arow[u];
        if (tid < 128) {
            const float* brow = W + (size_t)(n0 + nB) * E + k0 + khB;
#pragma unroll
            for (int u = 0; u < 5; u++) bv5[u] = brow[u];
        }
        __syncthreads();
#pragma unroll
        for (int u = 0; u < 5; u++) As[khA + u][mA] = av5[u];
        if (tid < 128) {
#pragma unroll
            for (int u = 0; u < 5; u++) Bs[khB + u][nB] = bv5[u];
        }
        __syncthreads();
#pragma unroll
        for (int kp = 0; kp < 5; kp++) {
            int kl = 2 * kp, kh = 2 * kp + 1;
            float4 aL0 = *(const float4*)&As[kl][tr * 8];
            float4 aL1 = *(const float4*)&As[kl][tr * 8 + 4];
            float4 aH0 = *(const float4*)&As[kh][tr * 8];
            float4 aH1 = *(const float4*)&As[kh][tr * 8 + 4];
            float4 bL  = *(const float4*)&Bs[kl][tc * 4];
            float4 bH  = *(const float4*)&Bs[kh][tc * 4];
            u64 ap[8], bp[4];
            ap[0] = pk2(aL0.x, aH0.x); ap[1] = pk2(aL0.y, aH0.y);
            ap[2] = pk2(aL0.z, aH0.z); ap[3] = pk2(aL0.w, aH0.w);
            ap[4] = pk2(aL1.x, aH1.x); ap[5] = pk2(aL1.y, aH1.y);
            ap[6] = pk2(aL1.z, aH1.z); ap[7] = pk2(aL1.w, aH1.w);
            bp[0] = pk2(bL.x, bH.x); bp[1] = pk2(bL.y, bH.y);
            bp[2] = pk2(bL.z, bH.z); bp[3] = pk2(bL.w, bH.w);
#pragma unroll
            for (int i = 0; i < 8; i++)
#pragma unroll
                for (int j = 0; j < 4; j++) acc[i][j] = ffma2(ap[i], bp[j], acc[i][j]);
        }
    }

#pragma unroll
    for (int i = 0; i < 8; i++) {
        int m = m0 + tr * 8 + i;
        int s = m >> 6, l = m & 63;
        int dj = (l == 63) ? 9 : dep[s * 63 + l];
        const float* dqrow = g_dq + dj * NH3 + n0 + tc * 4;
        float* outr = ((l == 63) ? (g_leaf + (size_t)s * NH3)
                                 : (g_pre + (size_t)(s * 63 + l) * NH3)) + n0 + tc * 4;
        float4 dq4 = *(const float4*)dqrow;
        float4 v;
        v.x = pairsum(acc[i][0]) + bsh[tc * 4 + 0] + dq4.x;
        v.y = pairsum(acc[i][1]) + bsh[tc * 4 + 1] + dq4.y;
        v.z = pairsum(acc[i][2]) + bsh[tc * 4 + 2] + dq4.z;
        v.w = pairsum(acc[i][3]) + bsh[tc * 4 + 3] + dq4.w;
        *(float4*)outr = v;
    }
}

// ---------------- leaf: h = tanh(sigmoid(iu_i) * tanh(iu_u)) ----------------
__global__ void leaf_kernel() {
    int idx = blockIdx.x * 256 + threadIdx.x;
    int s = idx >> 8, i = idx & 255;
    const float* r = g_leaf + (size_t)s * NH3;
    g_h[idx] = tanhf(sigf(r[256 + i]) * tanhf(r[512 + i]));
}

// ---------------- C_part = g_h @ B^T, split-K 4, FFMA2 w/ smem-packed k-pairs ----------------
// BM=128, BN=64, BK=16, 256 threads, 8x4 microtile (n strided by 16). grid (12, 8, 4)
#define ASTRIDE 134
#define BSTRIDE 66
__global__ __launch_bounds__(256) void ab_gemm(const float* __restrict__ B) {
    __shared__ __align__(16) u64 As2[8 * ASTRIDE];
    __shared__ __align__(16) u64 Bs2[8 * BSTRIDE];
    int tid = threadIdx.x;
    int n0 = blockIdx.x * 64, m0 = blockIdx.y * 128, kb = blockIdx.z * 64;

    u64 acc[8][4];
#pragma unroll
    for (int i = 0; i < 8; i++)
#pragma unroll
        for (int j = 0; j < 4; j++) acc[i][j] = 0ull;

    int mA = tid >> 1, kpa = (tid & 1) * 4;   // A: 8 floats = 4 k-pair rows
    int nB = tid >> 2, kpb = (tid & 3) * 2;   // B: 4 floats = 2 k-pair rows
    int tr = tid >> 4, tc = tid & 15;

    for (int it = 0; it < 4; it++) {
        int k0 = kb + it * 16;
        float4 a0 = *(const float4*)(g_h + (size_t)(m0 + mA) * H + k0 + kpa * 2);
        float4 a1 = *(const float4*)(g_h + (size_t)(m0 + mA) * H + k0 + kpa * 2 + 4);
        float4 b0 = *(const float4*)(B + (size_t)(n0 + nB) * H + k0 + kpb * 2);
        __syncthreads();
        As2[(kpa + 0) * ASTRIDE + mA] = pk2(a0.x, a0.y);
        As2[(kpa + 1) * ASTRIDE + mA] = pk2(a0.z, a0.w);
        As2[(kpa + 2) * ASTRIDE + mA] = pk2(a1.x, a1.y);
        As2[(kpa + 3) * ASTRIDE + mA] = pk2(a1.z, a1.w);
        Bs2[(kpb + 0) * BSTRIDE + nB] = pk2(b0.x, b0.y);
        Bs2[(kpb + 1) * BSTRIDE + nB] = pk2(b0.z, b0.w);
        __syncthreads();
#pragma unroll
        for (int kp = 0; kp < 8; kp++) {
            u64 av[8], bv[4];
            const u64* ar = &As2[kp * ASTRIDE + tr * 8];
#pragma unroll
            for (int i = 0; i < 8; i++) av[i] = ar[i];
#pragma unroll
            for (int j = 0; j < 4; j++) bv[j] = Bs2[kp * BSTRIDE + tc + 16 * j];
#pragma unroll
            for (int i = 0; i < 8; i++)
#pragma unroll
                for (int j = 0; j < 4; j++) acc[i][j] = ffma2(av[i], bv[j], acc[i][j]);
        }
    }
    float* Cw = (blockIdx.z == 0) ? g_pA : (blockIdx.z == 1) ? g_pB
              : (blockIdx.z == 2) ? g_pC : g_pD;
#pragma unroll
    for (int i = 0; i < 8; i++) {
        float* crow = Cw + (size_t)(m0 + tr * 8 + i) * NH3 + n0 + tc;
#pragma unroll
        for (int j = 0; j < 4; j++) crow[16 * j] = pairsum(acc[i][j]);
    }
}

// ---------------- tree elementwise step ----------------
__global__ void tree_elem_kernel(int k) {
    int idx = blockIdx.x * 256 + threadIdx.x;
    int s = idx >> 8, i = idx & 255;
    size_t pb = (size_t)(s * 63 + k) * NH3;
    size_t ab = (size_t)s * NH3;
    float t0 = g_pre[pb + i]       + g_pA[ab + i]       + g_pB[ab + i]       + g_pC[ab + i]       + g_pD[ab + i];
    float t1 = g_pre[pb + 256 + i] + g_pA[ab + 256 + i] + g_pB[ab + 256 + i] + g_pC[ab + 256 + i] + g_pD[ab + 256 + i];
    float t2 = g_pre[pb + 512 + i] + g_pA[ab + 512 + i] + g_pB[ab + 512 + i] + g_pC[ab + 512 + i] + g_pD[ab + 512 + i];
    float hc = g_h[idx];
    float f = sigf(t0) * hc;
    g_h[idx] = tanhf(sigf(t1) * tanhf(t2) + f);
}

// ---------------- gi = sv @ wih^T + bih ----------------
__global__ void gi_combine_kernel(const float* __restrict__ bih) {
    int idx = blockIdx.x * 256 + threadIdx.x;
    int n = idx % NH3;
    g_gi[idx] = g_pA[idx] + g_pB[idx] + g_pC[idx] + g_pD[idx] + bih[n];
}

// ---------------- GRU: 8-CTA cluster, R1 pull protocol, FFMA2 matvec ----------------
__device__ __forceinline__ uint32_t smem_u32(const void* p) {
    return (uint32_t)__cvta_generic_to_shared(p);
}
__device__ __forceinline__ uint32_t mapa_u32(uint32_t a, uint32_t r) {
    uint32_t o;
    asm("mapa.shared::cluster.u32 %0, %1, %2;" : "=r"(o) : "r"(a), "r"(r));
    return o;
}
__device__ __forceinline__ float ld_remote(uint32_t a) {
    float v;
    asm volatile("ld.shared::cluster.f32 %0, [%1];" : "=f"(v) : "r"(a) : "memory");
    return v;
}
__device__ __forceinline__ void cluster_barrier() {
    asm volatile("barrier.cluster.arrive.aligned;" ::: "memory");
    asm volatile("barrier.cluster.wait.aligned;" ::: "memory");
}

__global__ void __cluster_dims__(8, 1, 1) __launch_bounds__(256, 1)
gru_kernel(const float* __restrict__ whh, const float* __restrict__ bhh,
           const float* __restrict__ h0) {
    __shared__ __align__(16) float hsh[H];
    __shared__ float ghsh[2][96];

    int tid = threadIdx.x;
    unsigned rank;
    asm("mov.u32 %0, %%cluster_ctarank;" : "=r"(rank));
    int g = tid >> 3, p = tid & 7;
    int jbase = (int)rank * 96 + g * 3;

    // whh slice as packed k-pairs: 3 outputs x 16 pairs (k = p*32 ...)
    u64 wp[3][16];
    float bh[3];
#pragma unroll
    for (int c = 0; c < 3; c++) {
        int j = jbase + c;
        bh[c] = bhh[j];
        const float4* wr = (const float4*)(whh + (size_t)j * H + p * 32);
#pragma unroll
        for (int u = 0; u < 8; u++) {
            float4 v = wr[u];
            wp[c][2 * u]     = pk2(v.x, v.y);
            wp[c][2 * u + 1] = pk2(v.z, v.w);
        }
    }
    hsh[tid] = h0[tid];

    // pull addresses: gh[c*256 + tid] lives on rank (j/96) at offset j%96
    uint32_t radr[2][3];
#pragma unroll
    for (int par = 0; par < 2; par++)
#pragma unroll
        for (int c = 0; c < 3; c++) {
            int j = c * H + tid;
            radr[par][c] = mapa_u32(smem_u32(&ghsh[par][j % 96]), (uint32_t)(j / 96));
        }

    for (int t = 0; t < S_SENT; t++) {
        __syncthreads();
        int par = t & 1;
        const float* gir = g_gi + (size_t)t * NH3;
        float gi0 = __ldg(gir + tid), gi1 = __ldg(gir + 256 + tid), gi2 = __ldg(gir + 512 + tid);

        u64 hvp[16];
        const float4* hp = (const float4*)(hsh + p * 32);
#pragma unroll
        for (int u = 0; u < 8; u++) {
            float4 v = hp[u];
            hvp[2 * u]     = pk2(v.x, v.y);
            hvp[2 * u + 1] = pk2(v.z, v.w);
        }
        u64 pa0 = 0ull, pa1 = 0ull, pa2 = 0ull;
#pragma unroll
        for (int u = 0; u < 16; u++) {
            pa0 = ffma2(wp[0][u], hvp[u], pa0);
            pa1 = ffma2(wp[1][u], hvp[u], pa1);
            pa2 = ffma2(wp[2][u], hvp[u], pa2);
        }
        float a0 = pairsum(pa0), a1 = pairsum(pa1), a2 = pairsum(pa2);
#pragma unroll
        for (int off = 4; off > 0; off >>= 1) {
            a0 += __shfl_down_sync(0xffffffffu, a0, off, 8);
            a1 += __shfl_down_sync(0xffffffffu, a1, off, 8);
            a2 += __shfl_down_sync(0xffffffffu, a2, off, 8);
        }
        if (p == 0) {
            ghsh[par][g * 3 + 0] = a0 + bh[0];
            ghsh[par][g * 3 + 1] = a1 + bh[1];
            ghsh[par][g * 3 + 2] = a2 + bh[2];
        }
        cluster_barrier();

        float gh0 = ld_remote(radr[par][0]);
        float gh1 = ld_remote(radr[par][1]);
        float gh2 = ld_remote(radr[par][2]);
        float hh = hsh[tid];
        float r = sigf(gi0 + gh0);
        float z = sigf(gi1 + gh1);
        float n = tanhf(gi2 + r * gh2);
        hsh[tid] = (1.0f - z) * n + z * hh;
    }
    __syncthreads();
    if (rank == 0) g_hT[tid] = hsh[tid];
}

// ---------------- final: topic, gate, classifier, softmax ----------------
__global__ void final_kernel(const float* __restrict__ DT,
                             const float* __restrict__ gate_W, const float* __restrict__ gate_U,
                             const float* __restrict__ gate_b,
                             const float* __restrict__ mlp_W, const float* __restrict__ mlp_b,
                             const float* __restrict__ out_W, const float* __restrict__ out_b,
                             float* __restrict__ out) {
    __shared__ float tsh[H], hsh[H], vsh[H], lg[NTGT];
    int tid = threadIdx.x;
    float acc = mlp_b[tid];
    const float* mr = mlp_W + (size_t)tid * NTOPIC;
#pragma unroll 4
    for (int k = 0; k < NTOPIC; k++) acc += mr[k] * DT[k];
    tsh[tid] = tanhf(acc);
    hsh[tid] = g_hT[tid];
    __syncthreads();
    float ga = gate_b[tid], gb = gate_b[tid + H];
    const float* wr = gate_W + (size_t)tid * H;
    const float* wr2 = gate_W + (size_t)(tid + H) * H;
    const float* ur = gate_U + (size_t)tid * H;
    const float* ur2 = gate_U + (size_t)(tid + H) * H;
#pragma unroll 4
    for (int k = 0; k < H; k++) {
        float hk = hsh[k], tk = tsh[k];
        ga += wr[k] * hk + ur[k] * tk;
        gb += wr2[k] * hk + ur2[k] * tk;
    }
    vsh[tid] = tanhf(sigf(ga) * hsh[tid] + sigf(gb) * tsh[tid]);
    __syncthreads();
    int wix = tid >> 5, lane = tid & 31;
    if (wix < NTGT) {
        float a = 0.f;
        for (int k = lane; k < H; k += 32) a += out_W[wix * H + k] * vsh[k];
#pragma unroll
        for (int off = 16; off > 0; off >>= 1) a += __shfl_down_sync(0xffffffffu, a, off);
        if (lane == 0) lg[wix] = a + out_b[wix];
    }
    __syncthreads();
    if (tid == 0) {
        float mx = lg[0];
        for (int i = 1; i < NTGT; i++) mx = fmaxf(mx, lg[i]);
        float s = 0.f, e[NTGT];
        for (int i = 0; i < NTGT; i++) { e[i] = expf(lg[i] - mx); s += e[i]; }
        for (int i = 0; i < NTGT; i++) out[i] = e[i] / s;
    }
}

extern "C" void kernel_launch(void* const* d_in, const int* in_sizes, int n_in,
                              void* d_out, int out_size) {
    const int*   sidx    = (const int*)  d_in[0];
    const int*   dep     = (const int*)  d_in[1];
    const float* DT      = (const float*)d_in[2];
    const float* h0      = (const float*)d_in[3];
    const float* idx2vec = (const float*)d_in[4];
    const float* q       = (const float*)d_in[5];
    const float* W       = (const float*)d_in[6];
    const float* U       = (const float*)d_in[7];
    const float* D       = (const float*)d_in[8];
    const float* b       = (const float*)d_in[9];
    const float* gru_wih = (const float*)d_in[10];
    const float* gru_whh = (const float*)d_in[11];
    const float* gru_bih = (const float*)d_in[12];
    const float* gru_bhh = (const float*)d_in[13];
    const float* gate_W  = (const float*)d_in[14];
    const float* gate_U  = (const float*)d_in[15];
    const float* gate_b  = (const float*)d_in[16];
    const float* mlp_W   = (const float*)d_in[17];
    const float* mlp_b   = (const float*)d_in[18];
    const float* out_W   = (const float*)d_in[19];
    const float* out_b   = (const float*)d_in[20];
    float* out = (float*)d_out;

    prep_kernel<<<10, NH3>>>(D, q);
    wx_kernel<<<dim3(12, 512), 256>>>(sidx, dep, idx2vec, W, b);
    leaf_kernel<<<1024, 256>>>();

    for (int k = L_W - 2; k >= 0; k--) {
        ab_gemm<<<dim3(12, 8, 4), 256>>>(U);
        tree_elem_kernel<<<1024, 256>>>(k);
    }

    ab_gemm<<<dim3(12, 8, 4), 256>>>(gru_wih);
    gi_combine_kernel<<<3072, 256>>>(gru_bih);

    gru_kernel<<<8, 256>>>(gru_whh, gru_bhh, h0);

    final_kernel<<<1, 256>>>(DT, gate_W, gate_U, gate_b, mlp_W, mlp_b, out_W, out_b, out);
}

// round 8
// speedup vs baseline: 1.2084x; 1.1117x over previous
#include <cuda_runtime.h>
#include <cuda_bf16.h>
#include <cstdint>
#include <math.h>

#define H      256
#define E      300
#define S_SENT 1024
#define L_W    64
#define NH3    768
#define NTOPIC 100
#define NTGT   5
#define KSPLIT 8

typedef unsigned long long u64;

// ---------------- scratch ----------------
__device__ float g_dq[10 * NH3];
__device__ float g_pre[S_SENT * (L_W - 1) * NH3];
__device__ float g_leaf[S_SENT * NH3];
__device__ float g_h[S_SENT * H];
__device__ float g_part[KSPLIT * S_SENT * NH3];
__device__ float g_gi[S_SENT * NH3];
__device__ float g_hT[H];

__device__ __forceinline__ float sigf(float x) { return 1.0f / (1.0f + expf(-x)); }

// ---- packed fp32x2 helpers (GRU only) ----
__device__ __forceinline__ u64 pk2(float lo, float hi) {
    u64 r; asm("mov.b64 %0, {%1, %2};" : "=l"(r) : "f"(lo), "f"(hi)); return r;
}
__device__ __forceinline__ u64 ffma2(u64 a, u64 b, u64 c) {
    u64 d; asm("fma.rn.f32x2 %0, %1, %2, %3;" : "=l"(d) : "l"(a), "l"(b), "l"(c)); return d;
}
__device__ __forceinline__ float pairsum(u64 v) {
    float x, y; asm("mov.b64 {%0, %1}, %2;" : "=f"(x), "=f"(y) : "l"(v)); return x + y;
}

// ---------------- dep-type table ----------------
__global__ void prep_kernel(const float* __restrict__ D, const float* __restrict__ q) {
    __shared__ float qs[H];
    int t = blockIdx.x;
    if (threadIdx.x < H) qs[threadIdx.x] = q[t * H + threadIdx.x];
    __syncthreads();
    int j = threadIdx.x;
    const float* Drow = D + (size_t)j * H;
    float acc = 0.f;
#pragma unroll 8
    for (int k = 0; k < H; k++) acc += Drow[k] * qs[k];
    g_dq[t * NH3 + j] = acc;
}

// ---------------- Wx GEMM with embedding gather (R1 version, 128x128) ----------------
__global__ __launch_bounds__(256) void wx_kernel(
    const int* __restrict__ sidx, const int* __restrict__ dep,
    const float* __restrict__ idx2vec, const float* __restrict__ W,
    const float* __restrict__ bias) {
    __shared__ float As[10][132];
    __shared__ float Bs[10][132];
    __shared__ int   ridx[128];
    __shared__ float bsh[128];

    int tid = threadIdx.x;
    int m0 = blockIdx.y * 128, n0 = blockIdx.x * 128;
    if (tid < 128) { ridx[tid] = sidx[m0 + tid]; bsh[tid] = bias[n0 + tid]; }
    __syncthreads();

    float acc[8][8];
#pragma unroll
    for (int i = 0; i < 8; i++)
#pragma unroll
        for (int j = 0; j < 8; j++) acc[i][j] = 0.f;

    int mA = tid >> 1;
    int khA = (tid & 1) * 5;
    int tr = tid >> 4, tc = tid & 15;

    for (int kt = 0; kt < 30; kt++) {
        int k0 = kt * 10;
        const float* arow = idx2vec + (size_t)ridx[mA] * E + k0 + khA;
        const float* brow = W + (size_t)(n0 + mA) * E + k0 + khA;
        float av5[5], bv5[5];
#pragma unroll
        for (int u = 0; u < 5; u++) { av5[u] = arow[u]; bv5[u] = brow[u]; }
        __syncthreads();
#pragma unroll
        for (int u = 0; u < 5; u++) {
            As[khA + u][mA] = av5[u];
            Bs[khA + u][mA] = bv5[u];
        }
        __syncthreads();
#pragma unroll
        for (int kk = 0; kk < 10; kk++) {
            float4 a0 = *(const float4*)&As[kk][tr * 8];
            float4 a1 = *(const float4*)&As[kk][tr * 8 + 4];
            float4 b0 = *(const float4*)&Bs[kk][tc * 8];
            float4 b1 = *(const float4*)&Bs[kk][tc * 8 + 4];
            float av[8] = {a0.x, a0.y, a0.z, a0.w, a1.x, a1.y, a1.z, a1.w};
            float bv[8] = {b0.x, b0.y, b0.z, b0.w, b1.x, b1.y, b1.z, b1.w};
#pragma unroll
            for (int i = 0; i < 8; i++)
#pragma unroll
                for (int j = 0; j < 8; j++) acc[i][j] += av[i] * bv[j];
        }
    }

#pragma unroll
    for (int i = 0; i < 8; i++) {
        int m = m0 + tr * 8 + i;
        int s = m >> 6, l = m & 63;
        int dj = (l == 63) ? 9 : dep[s * 63 + l];
        const float* dqrow = g_dq + dj * NH3;
        float* outr = (l == 63) ? (g_leaf + (size_t)s * NH3)
                                : (g_pre + (size_t)(s * 63 + l) * NH3);
#pragma unroll
        for (int j = 0; j < 8; j++) {
            int n = tc * 8 + j;
            outr[n0 + n] = acc[i][j] + bsh[n] + dqrow[n0 + n];
        }
    }
}

// ---------------- leaf: h = tanh(sigmoid(iu_i) * tanh(iu_u)) ----------------
__global__ void leaf_kernel() {
    int idx = blockIdx.x * 256 + threadIdx.x;
    int s = idx >> 8, i = idx & 255;
    const float* r = g_leaf + (size_t)s * NH3;
    g_h[idx] = tanhf(sigf(r[256 + i]) * tanhf(r[512 + i]));
}

// ---------------- C_part = g_h @ B^T  (split-K 8: grid (12, 8, 8)) ----------------
// BM=128, BN=64, BK=16, 256 threads, 8x4 microtile
__global__ __launch_bounds__(256) void ab_gemm(const float* __restrict__ B) {
    __shared__ float As[16][132];
    __shared__ float Bs[16][72];
    int tid = threadIdx.x;
    int n0 = blockIdx.x * 64, m0 = blockIdx.y * 128, kb = blockIdx.z * 32;

    float acc[8][4];
#pragma unroll
    for (int i = 0; i < 8; i++)
#pragma unroll
        for (int j = 0; j < 4; j++) acc[i][j] = 0.f;

    int mA = tid >> 1, khA = (tid & 1) * 8;
    int nB = tid >> 2, kqB = (tid & 3) * 4;
    int tr = tid >> 4, tc = tid & 15;

    for (int it = 0; it < 2; it++) {
        int k0 = kb + it * 16;
        float4 a0 = *(const float4*)(g_h + (size_t)(m0 + mA) * H + k0 + khA);
        float4 a1 = *(const float4*)(g_h + (size_t)(m0 + mA) * H + k0 + khA + 4);
        float4 b0 = *(const float4*)(B + (size_t)(n0 + nB) * H + k0 + kqB);
        __syncthreads();
        As[khA + 0][mA] = a0.x; As[khA + 1][mA] = a0.y;
        As[khA + 2][mA] = a0.z; As[khA + 3][mA] = a0.w;
        As[khA + 4][mA] = a1.x; As[khA + 5][mA] = a1.y;
        As[khA + 6][mA] = a1.z; As[khA + 7][mA] = a1.w;
        Bs[kqB + 0][nB] = b0.x; Bs[kqB + 1][nB] = b0.y;
        Bs[kqB + 2][nB] = b0.z; Bs[kqB + 3][nB] = b0.w;
        __syncthreads();
#pragma unroll
        for (int kk = 0; kk < 16; kk++) {
            float4 a0v = *(const float4*)&As[kk][tr * 8];
            float4 a1v = *(const float4*)&As[kk][tr * 8 + 4];
            float4 bv = *(const float4*)&Bs[kk][tc * 4];
            float av[8] = {a0v.x, a0v.y, a0v.z, a0v.w, a1v.x, a1v.y, a1v.z, a1v.w};
#pragma unroll
            for (int i = 0; i < 8; i++) {
                acc[i][0] += av[i] * bv.x;
                acc[i][1] += av[i] * bv.y;
                acc[i][2] += av[i] * bv.z;
                acc[i][3] += av[i] * bv.w;
            }
        }
    }
    float* Cw = g_part + (size_t)blockIdx.z * (S_SENT * NH3);
#pragma unroll
    for (int i = 0; i < 8; i++) {
        float4 v = make_float4(acc[i][0], acc[i][1], acc[i][2], acc[i][3]);
        *(float4*)(Cw + (size_t)(m0 + tr * 8 + i) * NH3 + n0 + tc * 4) = v;
    }
}

// ---------------- tree elementwise step (sums 8 partials) ----------------
__global__ void tree_elem_kernel(int k) {
    int idx = blockIdx.x * 256 + threadIdx.x;
    int s = idx >> 8, i = idx & 255;
    size_t pb = (size_t)(s * 63 + k) * NH3;
    size_t ab = (size_t)s * NH3;
    float t0 = g_pre[pb + i];
    float t1 = g_pre[pb + 256 + i];
    float t2 = g_pre[pb + 512 + i];
#pragma unroll
    for (int z = 0; z < KSPLIT; z++) {
        const float* pz = g_part + (size_t)z * (S_SENT * NH3) + ab;
        t0 += pz[i];
        t1 += pz[256 + i];
        t2 += pz[512 + i];
    }
    float hc = g_h[idx];
    float f = sigf(t0) * hc;
    g_h[idx] = tanhf(sigf(t1) * tanhf(t2) + f);
}

// ---------------- gi = sv @ wih^T + bih ----------------
__global__ void gi_combine_kernel(const float* __restrict__ bih) {
    int idx = blockIdx.x * 256 + threadIdx.x;
    int n = idx % NH3;
    float v = bih[n];
#pragma unroll
    for (int z = 0; z < KSPLIT; z++)
        v += g_part[(size_t)z * (S_SENT * NH3) + idx];
    g_gi[idx] = v;
}

// ---------------- GRU: 8-CTA cluster, pull protocol, FFMA2 matvec ----------------
__device__ __forceinline__ uint32_t smem_u32(const void* p) {
    return (uint32_t)__cvta_generic_to_shared(p);
}
__device__ __forceinline__ uint32_t mapa_u32(uint32_t a, uint32_t r) {
    uint32_t o;
    asm("mapa.shared::cluster.u32 %0, %1, %2;" : "=r"(o) : "r"(a), "r"(r));
    return o;
}
__device__ __forceinline__ float ld_remote(uint32_t a) {
    float v;
    asm volatile("ld.shared::cluster.f32 %0, [%1];" : "=f"(v) : "r"(a) : "memory");
    return v;
}
__device__ __forceinline__ void cluster_barrier() {
    asm volatile("barrier.cluster.arrive.aligned;" ::: "memory");
    asm volatile("barrier.cluster.wait.aligned;" ::: "memory");
}

__global__ void __cluster_dims__(8, 1, 1) __launch_bounds__(256, 1)
gru_kernel(const float* __restrict__ whh, const float* __restrict__ bhh,
           const float* __restrict__ h0) {
    __shared__ __align__(16) float hsh[H];
    __shared__ float ghsh[2][96];

    int tid = threadIdx.x;
    unsigned rank;
    asm("mov.u32 %0, %%cluster_ctarank;" : "=r"(rank));
    int g = tid >> 3, p = tid & 7;
    int jbase = (int)rank * 96 + g * 3;

    u64 wp[3][16];
    float bh[3];
#pragma unroll
    for (int c = 0; c < 3; c++) {
        int j = jbase + c;
        bh[c] = bhh[j];
        const float4* wr = (const float4*)(whh + (size_t)j * H + p * 32);
#pragma unroll
        for (int u = 0; u < 8; u++) {
            float4 v = wr[u];
            wp[c][2 * u]     = pk2(v.x, v.y);
            wp[c][2 * u + 1] = pk2(v.z, v.w);
        }
    }
    hsh[tid] = h0[tid];

    uint32_t radr[2][3];
#pragma unroll
    for (int par = 0; par < 2; par++)
#pragma unroll
        for (int c = 0; c < 3; c++) {
            int j = c * H + tid;
            radr[par][c] = mapa_u32(smem_u32(&ghsh[par][j % 96]), (uint32_t)(j / 96));
        }

    for (int t = 0; t < S_SENT; t++) {
        __syncthreads();
        int par = t & 1;
        const float* gir = g_gi + (size_t)t * NH3;
        float gi0 = __ldg(gir + tid), gi1 = __ldg(gir + 256 + tid), gi2 = __ldg(gir + 512 + tid);

        u64 hvp[16];
        const float4* hp = (const float4*)(hsh + p * 32);
#pragma unroll
        for (int u = 0; u < 8; u++) {
            float4 v = hp[u];
            hvp[2 * u]     = pk2(v.x, v.y);
            hvp[2 * u + 1] = pk2(v.z, v.w);
        }
        u64 pa0 = 0ull, pa1 = 0ull, pa2 = 0ull;
#pragma unroll
        for (int u = 0; u < 16; u++) {
            pa0 = ffma2(wp[0][u], hvp[u], pa0);
            pa1 = ffma2(wp[1][u], hvp[u], pa1);
            pa2 = ffma2(wp[2][u], hvp[u], pa2);
        }
        float a0 = pairsum(pa0), a1 = pairsum(pa1), a2 = pairsum(pa2);
#pragma unroll
        for (int off = 4; off > 0; off >>= 1) {
            a0 += __shfl_down_sync(0xffffffffu, a0, off, 8);
            a1 += __shfl_down_sync(0xffffffffu, a1, off, 8);
            a2 += __shfl_down_sync(0xffffffffu, a2, off, 8);
        }
        if (p == 0) {
            ghsh[par][g * 3 + 0] = a0 + bh[0];
            ghsh[par][g * 3 + 1] = a1 + bh[1];
            ghsh[par][g * 3 + 2] = a2 + bh[2];
        }
        cluster_barrier();

        float gh0 = ld_remote(radr[par][0]);
        float gh1 = ld_remote(radr[par][1]);
        float gh2 = ld_remote(radr[par][2]);
        float hh = hsh[tid];
        float r = sigf(gi0 + gh0);
        float z = sigf(gi1 + gh1);
        float n = tanhf(gi2 + r * gh2);
        hsh[tid] = (1.0f - z) * n + z * hh;
    }
    __syncthreads();
    if (rank == 0) g_hT[tid] = hsh[tid];
}

// ---------------- final: topic, gate, classifier, softmax ----------------
__global__ void final_kernel(const float* __restrict__ DT,
                             const float* __restrict__ gate_W, const float* __restrict__ gate_U,
                             const float* __restrict__ gate_b,
                             const float* __restrict__ mlp_W, const float* __restrict__ mlp_b,
                             const float* __restrict__ out_W, const float* __restrict__ out_b,
                             float* __restrict__ out) {
    __shared__ float tsh[H], hsh[H], vsh[H], lg[NTGT];
    int tid = threadIdx.x;
    float acc = mlp_b[tid];
    const float* mr = mlp_W + (size_t)tid * NTOPIC;
#pragma unroll 4
    for (int k = 0; k < NTOPIC; k++) acc += mr[k] * DT[k];
    tsh[tid] = tanhf(acc);
    hsh[tid] = g_hT[tid];
    __syncthreads();
    float ga = gate_b[tid], gb = gate_b[tid + H];
    const float* wr = gate_W + (size_t)tid * H;
    const float* wr2 = gate_W + (size_t)(tid + H) * H;
    const float* ur = gate_U + (size_t)tid * H;
    const float* ur2 = gate_U + (size_t)(tid + H) * H;
#pragma unroll 4
    for (int k = 0; k < H; k++) {
        float hk = hsh[k], tk = tsh[k];
        ga += wr[k] * hk + ur[k] * tk;
        gb += wr2[k] * hk + ur2[k] * tk;
    }
    vsh[tid] = tanhf(sigf(ga) * hsh[tid] + sigf(gb) * tsh[tid]);
    __syncthreads();
    int wix = tid >> 5, lane = tid & 31;
    if (wix < NTGT) {
        float a = 0.f;
        for (int k = lane; k < H; k += 32) a += out_W[wix * H + k] * vsh[k];
#pragma unroll
        for (int off = 16; off > 0; off >>= 1) a += __shfl_down_sync(0xffffffffu, a, off);
        if (lane == 0) lg[wix] = a + out_b[wix];
    }
    __syncthreads();
    if (tid == 0) {
        float mx = lg[0];
        for (int i = 1; i < NTGT; i++) mx = fmaxf(mx, lg[i]);
        float s = 0.f, e[NTGT];
        for (int i = 0; i < NTGT; i++) { e[i] = expf(lg[i] - mx); s += e[i]; }
        for (int i = 0; i < NTGT; i++) out[i] = e[i] / s;
    }
}

extern "C" void kernel_launch(void* const* d_in, const int* in_sizes, int n_in,
                              void* d_out, int out_size) {
    const int*   sidx    = (const int*)  d_in[0];
    const int*   dep     = (const int*)  d_in[1];
    const float* DT      = (const float*)d_in[2];
    const float* h0      = (const float*)d_in[3];
    const float* idx2vec = (const float*)d_in[4];
    const float* q       = (const float*)d_in[5];
    const float* W       = (const float*)d_in[6];
    const float* U       = (const float*)d_in[7];
    const float* D       = (const float*)d_in[8];
    const float* b       = (const float*)d_in[9];
    const float* gru_wih = (const float*)d_in[10];
    const float* gru_whh = (const float*)d_in[11];
    const float* gru_bih = (const float*)d_in[12];
    const float* gru_bhh = (const float*)d_in[13];
    const float* gate_W  = (const float*)d_in[14];
    const float* gate_U  = (const float*)d_in[15];
    const float* gate_b  = (const float*)d_in[16];
    const float* mlp_W   = (const float*)d_in[17];
    const float* mlp_b   = (const float*)d_in[18];
    const float* out_W   = (const float*)d_in[19];
    const float* out_b   = (const float*)d_in[20];
    float* out = (float*)d_out;

    prep_kernel<<<10, NH3>>>(D, q);
    wx_kernel<<<dim3(6, 512), 256>>>(sidx, dep, idx2vec, W, b);
    leaf_kernel<<<1024, 256>>>();

    for (int k = L_W - 2; k >= 0; k--) {
        ab_gemm<<<dim3(12, 8, KSPLIT), 256>>>(U);
        tree_elem_kernel<<<1024, 256>>>(k);
    }

    ab_gemm<<<dim3(12, 8, KSPLIT), 256>>>(gru_wih);
    gi_combine_kernel<<<3072, 256>>>(gru_bih);

    gru_kernel<<<8, 256>>>(gru_whh, gru_bhh, h0);

    final_kernel<<<1, 256>>>(DT, gate_W, gate_U, gate_b, mlp_W, mlp_b, out_W, out_b, out);
}